// round 2
// baseline (speedup 1.0000x reference)
#include <cuda_runtime.h>
#include <cuda_fp16.h>

// Gaussian-splat render, round 2.
//   out[n,c] = sum_m exp(-0.5 * d^T C_m^-1 d) * cols[m,c]
//
// Changes vs R1 (87.6us, issue/latency-bound, occ=10.6%):
//  * Prep kernel builds per-Gaussian tables once:
//      - 6 lane-duplicated f32x2 coefficients (48B -> 3 LDS.128/Gaussian)
//      - colors as half2 {c,c} packed in uint4 (read via __ldg, off the LDS pipe)
//  * Weight via single ex2.approx.f16x2 per pixel-pair (halves MUFU load).
//  * Color accumulation in f16x2 FMA with f32 flush every 8 Gaussians.
//  * Split-Gaussian: each pair handled by 2 threads (1024 Gaussians each),
//    grid 148x448 -> 14 warps/SM for latency hiding; smem reduction at end.

typedef unsigned long long u64;

static constexpr int N_GAUSS = 2048;
static constexpr int N_PAIR  = 32768;       // 65536 pixels / 2
static constexpr int BLK     = 448;
static constexpr int GRID    = 148;
static constexpr int SLOT    = 224;         // pairs per CTA slot group
static constexpr int HALF_G  = N_GAUSS / 2; // Gaussians per thread
static constexpr size_t SMEM_BYTES = (size_t)N_GAUSS * 6 * sizeof(u64); // 96KB

__device__ u64   g_coeff[N_GAUSS * 6];
__device__ uint4 g_cols[N_GAUSS];

__device__ __forceinline__ u64 pack2(float lo, float hi) {
    u64 r; asm("mov.b64 %0, {%1, %2};" : "=l"(r) : "f"(lo), "f"(hi)); return r;
}
__device__ __forceinline__ u64 fma2(u64 a, u64 b, u64 c) {
    u64 d; asm("fma.rn.f32x2 %0, %1, %2, %3;" : "=l"(d) : "l"(a), "l"(b), "l"(c)); return d;
}
__device__ __forceinline__ u64 mul2(u64 a, u64 b) {
    u64 d; asm("mul.rn.f32x2 %0, %1, %2;" : "=l"(d) : "l"(a), "l"(b)); return d;
}
// f32x2 -> packed half2 (low half = low f32 lane)
__device__ __forceinline__ unsigned cvt_h2(u64 t) {
    float lo, hi; unsigned r;
    asm("mov.b64 {%0, %1}, %2;" : "=f"(lo), "=f"(hi) : "l"(t));
    asm("cvt.rn.f16x2.f32 %0, %1, %2;" : "=r"(r) : "f"(hi), "f"(lo));
    return r;
}
__device__ __forceinline__ unsigned ex2_h2(unsigned v) {
    unsigned r; asm("ex2.approx.f16x2 %0, %1;" : "=r"(r) : "r"(v)); return r;
}
__device__ __forceinline__ unsigned hfma2(unsigned a, unsigned b, unsigned c) {
    unsigned d; asm("fma.rn.f16x2 %0, %1, %2, %3;" : "=r"(d) : "r"(a), "r"(b), "r"(c)); return d;
}
__device__ __forceinline__ float2 h2f(unsigned v) {
    __half2 h = *reinterpret_cast<__half2*>(&v);
    return __half22float2(h);
}

// ---- Prep: per-Gaussian coefficient + color tables ----
__global__ void prep_kernel(const float* __restrict__ mus,
                            const float* __restrict__ covs,
                            const float* __restrict__ cols)
{
    int m = blockIdx.x * blockDim.x + threadIdx.x;
    if (m >= N_GAUSS) return;

    const float s = -0.72134752044448170368f;  // -0.5 * log2(e)
    float2 mu = ((const float2*)mus)[m];
    float4 cv = ((const float4*)covs)[m];      // [a, b, b, c]
    float a = cv.x, b = cv.y, c = cv.w;
    float inv_det = 1.0f / (a * c - b * b);
    float p00 =  c * inv_det;
    float p01 = -b * inv_det;
    float p11 =  a * inv_det;

    float cxx = s * p00;
    float cxy = s * (2.0f * p01);
    float cyy = s * p11;
    float l1 = p00 * mu.x + p01 * mu.y;
    float l2 = p01 * mu.x + p11 * mu.y;
    float cx = s * (-2.0f * l1);
    float cy = s * (-2.0f * l2);
    float c0 = s * (mu.x * l1 + mu.y * l2);

    u64* q = g_coeff + (size_t)m * 6;
    q[0] = pack2(cxx, cxx);
    q[1] = pack2(cxy, cxy);
    q[2] = pack2(cyy, cyy);
    q[3] = pack2(cx,  cx);
    q[4] = pack2(cy,  cy);
    q[5] = pack2(c0,  c0);

    float r = cols[3 * m + 0];
    float g = cols[3 * m + 1];
    float bl = cols[3 * m + 2];
    __half2 hr = __floats2half2_rn(r,  r);
    __half2 hg = __floats2half2_rn(g,  g);
    __half2 hb = __floats2half2_rn(bl, bl);
    uint4 u;
    u.x = *reinterpret_cast<unsigned*>(&hr);
    u.y = *reinterpret_cast<unsigned*>(&hg);
    u.z = *reinterpret_cast<unsigned*>(&hb);
    u.w = 0;
    g_cols[m] = u;
}

// ---- Main render ----
__global__ __launch_bounds__(BLK, 1)
void render_kernel(const float* __restrict__ x, float* __restrict__ out)
{
    extern __shared__ u64 sh[];
    const int tid = threadIdx.x;

    // bulk copy coefficient table into shared
    {
        const ulonglong2* src = (const ulonglong2*)g_coeff;
        ulonglong2* dst = (ulonglong2*)sh;
        for (int i = tid; i < N_GAUSS * 3; i += BLK) dst[i] = src[i];
    }
    __syncthreads();

    const int hgrp = (tid >= SLOT) ? 1 : 0;
    const int slot = tid - hgrp * SLOT;
    const int p = blockIdx.x + GRID * slot;      // round-robin pair index
    const bool active = (p < N_PAIR);
    const int pc = active ? p : 0;

    // pixels 2p, 2p+1
    float4 xv = ((const float4*)x)[pc];
    u64 X1 = pack2(xv.x, xv.z);
    u64 X2 = pack2(xv.y, xv.w);
    u64 XX = mul2(X1, X1);
    u64 XY = mul2(X1, X2);
    u64 YY = mul2(X2, X2);

    float aR0 = 0.f, aR1 = 0.f, aG0 = 0.f, aG1 = 0.f, aB0 = 0.f, aB1 = 0.f;

    const ulonglong2* S = (const ulonglong2*)sh;
    const int mbase = hgrp * HALF_G;

    for (int blk = 0; blk < HALF_G / 8; ++blk) {
        unsigned hR = 0u, hG = 0u, hB = 0u;      // packed {0h, 0h}
        #pragma unroll
        for (int j = 0; j < 8; ++j) {
            int m = mbase + blk * 8 + j;
            ulonglong2 v0 = S[m * 3 + 0];        // {cxx} {cxy}
            ulonglong2 v1 = S[m * 3 + 1];        // {cyy} {cx}
            ulonglong2 v2 = S[m * 3 + 2];        // {cy}  {c0}
            uint4 cl = __ldg(&g_cols[m]);        // {h2 r, h2 g, h2 b, pad}

            u64 t = v2.y;                        // c0
            t = fma2(v0.x, XX, t);
            t = fma2(v0.y, XY, t);
            t = fma2(v1.x, YY, t);
            t = fma2(v1.y, X1, t);
            t = fma2(v2.x, X2, t);

            unsigned w = ex2_h2(cvt_h2(t));
            hR = hfma2(cl.x, w, hR);
            hG = hfma2(cl.y, w, hG);
            hB = hfma2(cl.z, w, hB);
        }
        float2 fr = h2f(hR); aR0 += fr.x; aR1 += fr.y;
        float2 fg = h2f(hG); aG0 += fg.x; aG1 += fg.y;
        float2 fb = h2f(hB); aB0 += fb.x; aB1 += fb.y;
    }

    // ---- cross-half reduction via shared (reuse coeff region) ----
    __syncthreads();                              // everyone done reading coeffs
    float* red = (float*)sh;
    if (hgrp) {
        float* q = red + slot * 6;
        q[0] = aR0; q[1] = aR1; q[2] = aG0; q[3] = aG1; q[4] = aB0; q[5] = aB1;
    }
    __syncthreads();
    if (!hgrp && active) {
        const float* q = red + slot * 6;
        float r0 = aR0 + q[0], r1 = aR1 + q[1];
        float g0 = aG0 + q[2], g1 = aG1 + q[3];
        float b0 = aB0 + q[4], b1 = aB1 + q[5];
        float2* o = (float2*)(out + (size_t)p * 6);
        o[0] = make_float2(r0, g0);
        o[1] = make_float2(b0, r1);
        o[2] = make_float2(g1, b1);
    }
}

extern "C" void kernel_launch(void* const* d_in, const int* in_sizes, int n_in,
                              void* d_out, int out_size)
{
    const float* x    = (const float*)d_in[0];
    const float* mus  = (const float*)d_in[1];
    const float* covs = (const float*)d_in[2];
    const float* cols = (const float*)d_in[3];
    float* out = (float*)d_out;

    prep_kernel<<<(N_GAUSS + 255) / 256, 256>>>(mus, covs, cols);

    cudaFuncSetAttribute(render_kernel,
                         cudaFuncAttributeMaxDynamicSharedMemorySize,
                         (int)SMEM_BYTES);
    render_kernel<<<GRID, BLK, SMEM_BYTES>>>(x, out);
}

// round 3
// speedup vs baseline: 1.3249x; 1.3249x over previous
#include <cuda_runtime.h>

// Gaussian-splat render, round 3.
//   out[n,c] = sum_m exp(-0.5 * d^T C_m^-1 d) * cols[m,c]
//
// R1/R2 were L1TEX-bound (L1 ~70%): 5 memory ops per (pair,Gaussian).
// Fix: amortize Gaussian loads over P=4 pixel-pairs per thread.
//  * Prep kernel: per-Gaussian table of 10 lane-dup f32x2 values
//    (6 quadratic coeffs + 3 colors + pad) = 5 LDS.128 per Gaussian.
//  * Main: 8192 pair-slots x 4 Gaussian-quarters = 32768 threads,
//    148 CTAs x 224 threads. Each thread: 512 Gaussians x 4 pairs.
//  * Full f32 path (2x ex2.approx.f32, f32x2 color fma) -> rel_err ~1e-6.
//  * Cross-quarter reduction through shared memory (coeff region reused).

typedef unsigned long long u64;

static constexpr int N_GAUSS = 2048;
static constexpr int N_PAIR  = 32768;        // 65536 pixels / 2
static constexpr int P       = 4;            // pairs per thread
static constexpr int Q       = 4;            // Gaussian quarters
static constexpr int GQ      = N_GAUSS / Q;  // 512 per thread
static constexpr int NSLOT   = N_PAIR / P;   // 8192 pair-slots
static constexpr int BLK     = 224;          // 56 slots x 4 quarters
static constexpr int SPB     = BLK / Q;      // 56 slots per CTA
static constexpr int GRID    = 148;
static constexpr int SLOTS   = 10;           // u64 per Gaussian (5 x LDS.128)
static constexpr size_t SMEM_BYTES = (size_t)N_GAUSS * SLOTS * sizeof(u64); // 160KB

__device__ u64 g_tab[N_GAUSS * SLOTS];

__device__ __forceinline__ u64 pack2(float lo, float hi) {
    u64 r; asm("mov.b64 %0, {%1, %2};" : "=l"(r) : "f"(lo), "f"(hi)); return r;
}
__device__ __forceinline__ void unpack2(u64 v, float& lo, float& hi) {
    asm("mov.b64 {%0, %1}, %2;" : "=f"(lo), "=f"(hi) : "l"(v));
}
__device__ __forceinline__ u64 fma2(u64 a, u64 b, u64 c) {
    u64 d; asm("fma.rn.f32x2 %0, %1, %2, %3;" : "=l"(d) : "l"(a), "l"(b), "l"(c)); return d;
}
__device__ __forceinline__ u64 mul2(u64 a, u64 b) {
    u64 d; asm("mul.rn.f32x2 %0, %1, %2;" : "=l"(d) : "l"(a), "l"(b)); return d;
}
__device__ __forceinline__ float ex2f(float v) {
    float r; asm("ex2.approx.f32 %0, %1;" : "=f"(r) : "f"(v)); return r;
}

// ---- Prep: per-Gaussian coefficient + color table (lane-duplicated) ----
__global__ void prep_kernel(const float* __restrict__ mus,
                            const float* __restrict__ covs,
                            const float* __restrict__ cols)
{
    int m = blockIdx.x * blockDim.x + threadIdx.x;
    if (m >= N_GAUSS) return;

    const float s = -0.72134752044448170368f;  // -0.5 * log2(e)
    float2 mu = ((const float2*)mus)[m];
    float4 cv = ((const float4*)covs)[m];      // [a, b, b, c]
    float a = cv.x, b = cv.y, c = cv.w;
    float inv_det = 1.0f / (a * c - b * b);
    float p00 =  c * inv_det;
    float p01 = -b * inv_det;
    float p11 =  a * inv_det;

    float cxx = s * p00;
    float cxy = s * (2.0f * p01);
    float cyy = s * p11;
    float l1 = p00 * mu.x + p01 * mu.y;
    float l2 = p01 * mu.x + p11 * mu.y;
    float cx = s * (-2.0f * l1);
    float cy = s * (-2.0f * l2);
    float c0 = s * (mu.x * l1 + mu.y * l2);

    float r  = cols[3 * m + 0];
    float g  = cols[3 * m + 1];
    float bl = cols[3 * m + 2];

    u64* q = g_tab + (size_t)m * SLOTS;
    q[0] = pack2(cxx, cxx);
    q[1] = pack2(cxy, cxy);
    q[2] = pack2(cyy, cyy);
    q[3] = pack2(cx,  cx);
    q[4] = pack2(cy,  cy);
    q[5] = pack2(c0,  c0);
    q[6] = pack2(r,   r);
    q[7] = pack2(g,   g);
    q[8] = pack2(bl,  bl);
    q[9] = 0ull;
}

// ---- Main render ----
__global__ __launch_bounds__(BLK, 1)
void render_kernel(const float* __restrict__ x, float* __restrict__ out)
{
    extern __shared__ u64 sh[];
    const int tid = threadIdx.x;

    // bulk copy table into shared
    {
        const ulonglong2* src = (const ulonglong2*)g_tab;
        ulonglong2* dst = (ulonglong2*)sh;
        #pragma unroll 4
        for (int i = tid; i < N_GAUSS * SLOTS / 2; i += BLK) dst[i] = src[i];
    }
    __syncthreads();

    const int quarter = tid / SPB;               // 0..3 (some warps straddle; ok)
    const int slot    = tid - quarter * SPB;     // 0..55
    const int sg      = blockIdx.x * SPB + slot; // global pair-slot
    const bool active = (sg < NSLOT);
    const int sgc     = active ? sg : 0;

    // P=4 pairs per thread, strided by NSLOT -> coalesced float4 loads
    u64 X1[P], X2[P], XX[P], XY[P], YY[P];
    u64 aR[P], aG[P], aB[P];
    #pragma unroll
    for (int i = 0; i < P; ++i) {
        float4 xv = ((const float4*)x)[sgc + NSLOT * i];
        X1[i] = pack2(xv.x, xv.z);
        X2[i] = pack2(xv.y, xv.w);
        XX[i] = mul2(X1[i], X1[i]);
        XY[i] = mul2(X1[i], X2[i]);
        YY[i] = mul2(X2[i], X2[i]);
        aR[i] = 0ull; aG[i] = 0ull; aB[i] = 0ull;
    }

    const ulonglong2* S = (const ulonglong2*)sh;   // 5 x LDS.128 per Gaussian
    const int mbase = quarter * GQ;

    #pragma unroll 2
    for (int j = 0; j < GQ; ++j) {
        const int m = mbase + j;
        ulonglong2 v0 = S[m * 5 + 0];  // {cxx} {cxy}
        ulonglong2 v1 = S[m * 5 + 1];  // {cyy} {cx }
        ulonglong2 v2 = S[m * 5 + 2];  // {cy } {c0 }
        ulonglong2 v3 = S[m * 5 + 3];  // {r  } {g  }
        ulonglong2 v4 = S[m * 5 + 4];  // {b  } {pad}

        #pragma unroll
        for (int i = 0; i < P; ++i) {
            u64 t = v2.y;              // c0
            t = fma2(v0.x, XX[i], t);
            t = fma2(v0.y, XY[i], t);
            t = fma2(v1.x, YY[i], t);
            t = fma2(v1.y, X1[i], t);
            t = fma2(v2.x, X2[i], t);

            float tl, th;
            unpack2(t, tl, th);
            u64 w = pack2(ex2f(tl), ex2f(th));

            aR[i] = fma2(v3.x, w, aR[i]);
            aG[i] = fma2(v3.y, w, aG[i]);
            aB[i] = fma2(v4.x, w, aB[i]);
        }
    }

    // ---- cross-quarter reduction via shared (reuse coeff region) ----
    __syncthreads();                  // all reads of S done
    float* red = (float*)sh;          // [3 quarters][SPB slots][P pairs][6]
    if (quarter != 0) {
        float* q = red + (((quarter - 1) * SPB + slot) * P) * 6;
        #pragma unroll
        for (int i = 0; i < P; ++i) {
            float r0, r1, g0, g1, b0, b1;
            unpack2(aR[i], r0, r1);
            unpack2(aG[i], g0, g1);
            unpack2(aB[i], b0, b1);
            float* qq = q + i * 6;
            qq[0] = r0; qq[1] = r1; qq[2] = g0; qq[3] = g1; qq[4] = b0; qq[5] = b1;
        }
    }
    __syncthreads();
    if (quarter == 0 && active) {
        #pragma unroll
        for (int i = 0; i < P; ++i) {
            float r0, r1, g0, g1, b0, b1;
            unpack2(aR[i], r0, r1);
            unpack2(aG[i], g0, g1);
            unpack2(aB[i], b0, b1);
            #pragma unroll
            for (int qd = 0; qd < 3; ++qd) {
                const float* qq = red + (((qd * SPB + slot) * P) + i) * 6;
                r0 += qq[0]; r1 += qq[1];
                g0 += qq[2]; g1 += qq[3];
                b0 += qq[4]; b1 += qq[5];
            }
            const int p = sg + NSLOT * i;        // pair index
            float2* o = (float2*)(out + (size_t)p * 6);
            o[0] = make_float2(r0, g0);
            o[1] = make_float2(b0, r1);
            o[2] = make_float2(g1, b1);
        }
    }
}

extern "C" void kernel_launch(void* const* d_in, const int* in_sizes, int n_in,
                              void* d_out, int out_size)
{
    const float* x    = (const float*)d_in[0];
    const float* mus  = (const float*)d_in[1];
    const float* covs = (const float*)d_in[2];
    const float* cols = (const float*)d_in[3];
    float* out = (float*)d_out;

    prep_kernel<<<(N_GAUSS + 255) / 256, 256>>>(mus, covs, cols);

    cudaFuncSetAttribute(render_kernel,
                         cudaFuncAttributeMaxDynamicSharedMemorySize,
                         (int)SMEM_BYTES);
    render_kernel<<<GRID, BLK, SMEM_BYTES>>>(x, out);
}

// round 6
// speedup vs baseline: 1.4063x; 1.0614x over previous
#include <cuda_runtime.h>

// Gaussian-splat render, round 4.
//   out[n,c] = sum_m exp(-0.5 * d^T C_m^-1 d) * cols[m,c]
//
// R3 (76.3us): P=4 pair amortization fixed L1 (70->26%) but occ=10.9%
// (7 warps/SM) left FMA at 46% — latency-bound.
// R4: keep P=4; split Gaussians Q=8 (256 each) -> 65536 threads,
//     512/CTA = 16 warps/SM. quarter = tid>>6 so quarters are
//     warp-aligned (uniform LDS broadcast). Round-robin slots spread
//     the 13% slack evenly; inactive threads skip the loop.

typedef unsigned long long u64;

static constexpr int N_GAUSS = 2048;
static constexpr int N_PAIR  = 32768;        // 65536 pixels / 2
static constexpr int P       = 4;            // pairs per thread
static constexpr int Q       = 8;            // Gaussian slices
static constexpr int GQ      = N_GAUSS / Q;  // 256 per thread
static constexpr int NSLOT   = N_PAIR / P;   // 8192 pair-slots
static constexpr int SPB     = 64;           // slots per CTA (warp-aligned)
static constexpr int BLK     = SPB * Q;      // 512 threads
static constexpr int GRID    = 148;
static constexpr int SLOTS   = 10;           // u64 per Gaussian (5 x LDS.128)
static constexpr size_t SMEM_BYTES = (size_t)N_GAUSS * SLOTS * sizeof(u64); // 160KB

__device__ u64 g_tab[N_GAUSS * SLOTS];

__device__ __forceinline__ u64 pack2(float lo, float hi) {
    u64 r; asm("mov.b64 %0, {%1, %2};" : "=l"(r) : "f"(lo), "f"(hi)); return r;
}
__device__ __forceinline__ void unpack2(u64 v, float& lo, float& hi) {
    asm("mov.b64 {%0, %1}, %2;" : "=f"(lo), "=f"(hi) : "l"(v));
}
__device__ __forceinline__ u64 fma2(u64 a, u64 b, u64 c) {
    u64 d; asm("fma.rn.f32x2 %0, %1, %2, %3;" : "=l"(d) : "l"(a), "l"(b), "l"(c)); return d;
}
__device__ __forceinline__ u64 mul2(u64 a, u64 b) {
    u64 d; asm("mul.rn.f32x2 %0, %1, %2;" : "=l"(d) : "l"(a), "l"(b)); return d;
}
__device__ __forceinline__ float ex2f(float v) {
    float r; asm("ex2.approx.f32 %0, %1;" : "=f"(r) : "f"(v)); return r;
}

// ---- Prep: per-Gaussian coefficient + color table (lane-duplicated) ----
__global__ void prep_kernel(const float* __restrict__ mus,
                            const float* __restrict__ covs,
                            const float* __restrict__ cols)
{
    int m = blockIdx.x * blockDim.x + threadIdx.x;
    if (m >= N_GAUSS) return;

    const float s = -0.72134752044448170368f;  // -0.5 * log2(e)
    float2 mu = ((const float2*)mus)[m];
    float4 cv = ((const float4*)covs)[m];      // [a, b, b, c]
    float a = cv.x, b = cv.y, c = cv.w;
    float inv_det = 1.0f / (a * c - b * b);
    float p00 =  c * inv_det;
    float p01 = -b * inv_det;
    float p11 =  a * inv_det;

    float cxx = s * p00;
    float cxy = s * (2.0f * p01);
    float cyy = s * p11;
    float l1 = p00 * mu.x + p01 * mu.y;
    float l2 = p01 * mu.x + p11 * mu.y;
    float cx = s * (-2.0f * l1);
    float cy = s * (-2.0f * l2);
    float c0 = s * (mu.x * l1 + mu.y * l2);

    float r  = cols[3 * m + 0];
    float g  = cols[3 * m + 1];
    float bl = cols[3 * m + 2];

    u64* q = g_tab + (size_t)m * SLOTS;
    q[0] = pack2(cxx, cxx);
    q[1] = pack2(cxy, cxy);
    q[2] = pack2(cyy, cyy);
    q[3] = pack2(cx,  cx);
    q[4] = pack2(cy,  cy);
    q[5] = pack2(c0,  c0);
    q[6] = pack2(r,   r);
    q[7] = pack2(g,   g);
    q[8] = pack2(bl,  bl);
    q[9] = 0ull;
}

// ---- Main render ----
__global__ __launch_bounds__(BLK, 1)
void render_kernel(const float* __restrict__ x, float* __restrict__ out)
{
    extern __shared__ u64 sh[];
    const int tid = threadIdx.x;

    // bulk copy table into shared
    {
        const ulonglong2* src = (const ulonglong2*)g_tab;
        ulonglong2* dst = (ulonglong2*)sh;
        #pragma unroll 4
        for (int i = tid; i < N_GAUSS * SLOTS / 2; i += BLK) dst[i] = src[i];
    }
    __syncthreads();

    const int quarter = tid >> 6;                 // 0..7, warp-aligned (2 warps each)
    const int slot    = tid & (SPB - 1);          // 0..63
    const int sg      = blockIdx.x + GRID * slot; // round-robin pair-slot
    const bool active = (sg < NSLOT);

    u64 X1[P], X2[P], XX[P], XY[P], YY[P];
    u64 aR[P], aG[P], aB[P];

    if (active) {
        #pragma unroll
        for (int i = 0; i < P; ++i) {
            float4 xv = ((const float4*)x)[sg + NSLOT * i];
            X1[i] = pack2(xv.x, xv.z);
            X2[i] = pack2(xv.y, xv.w);
            XX[i] = mul2(X1[i], X1[i]);
            XY[i] = mul2(X1[i], X2[i]);
            YY[i] = mul2(X2[i], X2[i]);
            aR[i] = 0ull; aG[i] = 0ull; aB[i] = 0ull;
        }

        const ulonglong2* S = (const ulonglong2*)sh;   // 5 x LDS.128 per Gaussian
        const int mbase = quarter * GQ;

        #pragma unroll 4
        for (int j = 0; j < GQ; ++j) {
            const int m = mbase + j;
            ulonglong2 v0 = S[m * 5 + 0];  // {cxx} {cxy}
            ulonglong2 v1 = S[m * 5 + 1];  // {cyy} {cx }
            ulonglong2 v2 = S[m * 5 + 2];  // {cy } {c0 }
            ulonglong2 v3 = S[m * 5 + 3];  // {r  } {g  }
            ulonglong2 v4 = S[m * 5 + 4];  // {b  } {pad}

            #pragma unroll
            for (int i = 0; i < P; ++i) {
                u64 t = v2.y;              // c0
                t = fma2(v0.x, XX[i], t);
                t = fma2(v0.y, XY[i], t);
                t = fma2(v1.x, YY[i], t);
                t = fma2(v1.y, X1[i], t);
                t = fma2(v2.x, X2[i], t);

                float tl, th;
                unpack2(t, tl, th);
                u64 w = pack2(ex2f(tl), ex2f(th));

                aR[i] = fma2(v3.x, w, aR[i]);
                aG[i] = fma2(v3.y, w, aG[i]);
                aB[i] = fma2(v4.x, w, aB[i]);
            }
        }
    }

    // ---- cross-slice reduction via shared (reuse coeff region) ----
    __syncthreads();                  // all reads of S done
    float* red = (float*)sh;          // [Q-1][SPB][P][6]
    if (quarter != 0 && active) {
        float* q = red + (((quarter - 1) * SPB + slot) * P) * 6;
        #pragma unroll
        for (int i = 0; i < P; ++i) {
            float r0, r1, g0, g1, b0, b1;
            unpack2(aR[i], r0, r1);
            unpack2(aG[i], g0, g1);
            unpack2(aB[i], b0, b1);
            float* qq = q + i * 6;
            qq[0] = r0; qq[1] = r1; qq[2] = g0; qq[3] = g1; qq[4] = b0; qq[5] = b1;
        }
    }
    __syncthreads();
    if (quarter == 0 && active) {
        #pragma unroll
        for (int i = 0; i < P; ++i) {
            float r0, r1, g0, g1, b0, b1;
            unpack2(aR[i], r0, r1);
            unpack2(aG[i], g0, g1);
            unpack2(aB[i], b0, b1);
            #pragma unroll
            for (int qd = 0; qd < Q - 1; ++qd) {
                const float* qq = red + (((qd * SPB + slot) * P) + i) * 6;
                r0 += qq[0]; r1 += qq[1];
                g0 += qq[2]; g1 += qq[3];
                b0 += qq[4]; b1 += qq[5];
            }
            const int p = sg + NSLOT * i;        // pair index
            float2* o = (float2*)(out + (size_t)p * 6);
            o[0] = make_float2(r0, g0);
            o[1] = make_float2(b0, r1);
            o[2] = make_float2(g1, b1);
        }
    }
}

extern "C" void kernel_launch(void* const* d_in, const int* in_sizes, int n_in,
                              void* d_out, int out_size)
{
    const float* x    = (const float*)d_in[0];
    const float* mus  = (const float*)d_in[1];
    const float* covs = (const float*)d_in[2];
    const float* cols = (const float*)d_in[3];
    float* out = (float*)d_out;

    prep_kernel<<<(N_GAUSS + 255) / 256, 256>>>(mus, covs, cols);

    cudaFuncSetAttribute(render_kernel,
                         cudaFuncAttributeMaxDynamicSharedMemorySize,
                         (int)SMEM_BYTES);
    render_kernel<<<GRID, BLK, SMEM_BYTES>>>(x, out);
}